// round 11
// baseline (speedup 1.0000x reference)
#include <cuda_runtime.h>
#include <cuda_fp16.h>

#define H 512
#define W 512
#define NIMG 48
#define TR 8                    // output rows per block
#define P 256                   // half2 columns (512 px cols = full width)
#define BLOCK 256
#define SCALE 8192.0f           // 2^13, exact; keeps tiny medians out of fp16 subnormals
#define INVSCALE (1.0f / 8192.0f)

__device__ __forceinline__ unsigned h2u(__half2 h) { return *reinterpret_cast<unsigned*>(&h); }
__device__ __forceinline__ __half2  u2h(unsigned u) { return *reinterpret_cast<__half2*>(&u); }

// Cross-pair column: (lo = a.hi, hi = b.lo) — one PRMT.
__device__ __forceinline__ __half2 prm(__half2 a, __half2 b) {
    return u2h(__byte_perm(h2u(a), h2u(b), 0x5432));
}

__device__ __forceinline__ __half2 med3h(__half2 a, __half2 b, __half2 c) {
    return __hmax2(__hmin2(a, b), __hmin2(__hmax2(a, b), c));
}

__global__ __launch_bounds__(BLOCK)
void MedianFilter_22737556865485_kernel(const float* __restrict__ in,
                                        float* __restrict__ out) {
    __shared__ __half2 sm[TR + 2][P + 2];   // [row][0]=dup D0, [1..256]=data, [257]=dup D255

    const int t   = threadIdx.x;            // owns px cols (2t, 2t+1)
    const int r0  = blockIdx.x * TR;
    const int img = blockIdx.y;

    const float* base  = in  + (size_t)img * (H * W);
    float*       obase = out + (size_t)img * (H * W);

    // ---- Fill: rows r0-1 .. r0+TR (reflected), converted to scaled fp16x2 ----
#pragma unroll
    for (int r = 0; r < TR + 2; ++r) {
        int gr = r0 - 1 + r;
        gr = (gr < 0) ? 1 : ((gr >= H) ? (H - 2) : gr);    // reflect rows
        const float2 v = *reinterpret_cast<const float2*>(base + (size_t)gr * W + 2 * t);
        const __half2 h = __floats2half2_rn(v.x * SCALE, v.y * SCALE);
        sm[r][t + 1] = h;
        if (t == 0)     sm[r][0]     = h;   // left halo dup: only .hi (= col 1) is read
        if (t == P - 1) sm[r][P + 1] = h;   // right halo dup: only .lo (= col 510) is read
    }
    __syncthreads();

    // ---- Row-triples (min3/med3/max3 of horizontal neighbors) in half2,
    //      3-deep rotating history; each triple serves 3 vertical outputs. ----
    __half2 lo[3], mi[3], hi[3];

#pragma unroll
    for (int r = 0; r < 2; ++r) {           // prime with smem rows 0,1
        const __half2 A = sm[r][t], B = sm[r][t + 1], C = sm[r][t + 2];
        const __half2 l = prm(A, B), rr = prm(B, C);
        lo[r] = __hmin2(__hmin2(l, rr), B);
        hi[r] = __hmax2(__hmax2(l, rr), B);
        mi[r] = med3h(l, B, rr);
    }

    float* po = obase + (size_t)r0 * W + 2 * t;
#pragma unroll
    for (int i = 0; i < TR; ++i) {
        const int k = (i + 2) % 3;          // compile-time rotation (full unroll)
        {
            const __half2 A = sm[i + 2][t], B = sm[i + 2][t + 1], C = sm[i + 2][t + 2];
            const __half2 l = prm(A, B), rr = prm(B, C);
            lo[k] = __hmin2(__hmin2(l, rr), B);   // min of row triple
            hi[k] = __hmax2(__hmax2(l, rr), B);   // max of row triple
            mi[k] = med3h(l, B, rr);              // med of row triple
        }

        const __half2 Amx = __hmax2(__hmax2(lo[0], lo[1]), lo[2]);  // max of mins
        const __half2 Cmn = __hmin2(__hmin2(hi[0], hi[1]), hi[2]);  // min of maxes
        const __half2 Bmd = med3h(mi[0], mi[1], mi[2]);             // med of meds
        const __half2 m   = med3h(Amx, Bmd, Cmn);                   // median9 (2 px)

        const float2 o = __half22float2(m);
        *reinterpret_cast<float2*>(po) = make_float2(o.x * INVSCALE, o.y * INVSCALE);
        po += W;
    }
}

extern "C" void kernel_launch(void* const* d_in, const int* in_sizes, int n_in,
                              void* d_out, int out_size) {
    const float* in  = (const float*)d_in[0];
    float*       out = (float*)d_out;
    dim3 grid(H / TR, NIMG);                // (64, 48) = 3072 blocks
    MedianFilter_22737556865485_kernel<<<grid, BLOCK>>>(in, out);
}

// round 12
// speedup vs baseline: 1.2709x; 1.2709x over previous
#include <cuda_runtime.h>
#include <cstdint>

#define H 512
#define W 512
#define NIMG 48
#define TRB 16                  // output rows per block band
#define BLOCK 256
#define RD 8                    // smem ring depth (rows)

__device__ __forceinline__ float med3f(float a, float b, float c) {
    return fmaxf(fminf(a, b), fminf(fmaxf(a, b), c));
}

__device__ __forceinline__ void cp16(uint32_t daddr, const float* g) {
    asm volatile("cp.async.ca.shared.global [%0], [%1], 16;" :: "r"(daddr), "l"(g) : "memory");
}
__device__ __forceinline__ void cp_commit() {
    asm volatile("cp.async.commit_group;" ::: "memory");
}
template <int N> __device__ __forceinline__ void cp_wait() {
    asm volatile("cp.async.wait_group %0;" :: "n"(N) : "memory");
}

__global__ __launch_bounds__(BLOCK)
void MedianFilter_22737556865485_kernel(const float* __restrict__ in,
                                        float* __restrict__ out) {
    // 4-word guards front/back so the (SEL-discarded) edge LDS at word -1 / +512 is in-bounds.
    __shared__ float smem[4 + RD * W + 4];
    float* const ring = smem + 4;

    const int t    = threadIdx.x;
    const int r0   = blockIdx.x * TRB;
    const int img  = blockIdx.y;
    const bool t0  = (t == 0), t255 = (t == BLOCK - 1);

    const float* base  = in  + (size_t)img * (H * W);
    float*       obase = out + (size_t)img * (H * W);

    const uint32_t sb = (uint32_t)__cvta_generic_to_shared(ring);
    const int rr = t >> 7;          // which of the 2 rows this thread fills
    const int k  = t & 127;         // 16B chunk within the row

    // gmem row pointer for ring index j (row r0-1+j), reflected at both image edges.
    auto gRow = [&](int j) -> const float* {
        int g = r0 - 1 + j;
        g = (g < 0) ? 1 : g;
        g = (g >= H) ? (2 * H - 2 - g) : g;
        return base + (size_t)g * W;
    };
    // Fill rows (j, j+1) as one commit group: 256 threads x 16B, fully coalesced.
    auto fill2 = [&](int j) {
        const int jj = j + rr;
        cp16(sb + (uint32_t)(((jj & (RD - 1)) * W + k * 4) * 4), gRow(jj) + k * 4);
        cp_commit();
    };

    // Prologue: rows j=0..4 resident (G1: 0,1  G2: 2,3  G3: 4).
    fill2(0);
    fill2(2);
    if (t < 128) cp16(sb + (uint32_t)(((4 & (RD - 1)) * W + k * 4) * 4), gRow(4) + k * 4);
    cp_commit();

    // Row-triple history (per pixel column): lo/mi/hi over 3 horizontal neighbors.
    float loA[3], miA[3], hiA[3];   // px col 2t
    float loB[3], miB[3], hiB[3];   // px col 2t+1

    auto triple = [&](int j) {      // j, j%3 compile-time under full unroll
        const float* rowp = ring + (j & (RD - 1)) * W;
        const float2 m = *reinterpret_cast<const float2*>(rowp + 2 * t);
        const float a = t0   ? m.y : rowp[2 * t - 1];   // reflect col -1 -> 1
        const float d = t255 ? m.x : rowp[2 * t + 2];   // reflect col W -> W-2
        const int h = j % 3;
        loA[h] = fminf(fminf(a, m.x), m.y);
        hiA[h] = fmaxf(fmaxf(a, m.x), m.y);
        miA[h] = med3f(a, m.x, m.y);
        loB[h] = fminf(fminf(m.x, m.y), d);
        hiB[h] = fmaxf(fmaxf(m.x, m.y), d);
        miB[h] = med3f(m.x, m.y, d);
    };
    auto combine = [&](float2* po) {
        const float A0 = fmaxf(fmaxf(loA[0], loA[1]), loA[2]);
        const float C0 = fminf(fminf(hiA[0], hiA[1]), hiA[2]);
        const float B0 = med3f(miA[0], miA[1], miA[2]);
        const float A1 = fmaxf(fmaxf(loB[0], loB[1]), loB[2]);
        const float C1 = fminf(fminf(hiB[0], hiB[1]), hiB[2]);
        const float B1 = med3f(miB[0], miB[1], miB[2]);
        *po = make_float2(med3f(A0, B0, C0), med3f(A1, B1, C1));
    };

    // Prime history with rows j=0,1 (G1 complete after wait<2>).
    cp_wait<2>();
    __syncthreads();
    triple(0);
    triple(1);

    float* po = obase + (size_t)r0 * W + 2 * t;

#pragma unroll
    for (int i = 0; i < TRB / 2; ++i) {
        if (i < TRB / 2 - 1) {      // prefetch rows j=2i+5, 2i+6 (one group)
            fill2(2 * i + 5);
            cp_wait<1>();           // all but newest done -> rows j<=2i+4 ready
        } else {
            cp_wait<0>();           // final step: drain everything
        }
        __syncthreads();

        triple(2 * i + 2);          // row r0+2i+1
        combine(reinterpret_cast<float2*>(po));          // output row r0+2i
        triple(2 * i + 3);          // row r0+2i+2
        combine(reinterpret_cast<float2*>(po + W));      // output row r0+2i+1
        po += 2 * W;
    }
}

extern "C" void kernel_launch(void* const* d_in, const int* in_sizes, int n_in,
                              void* d_out, int out_size) {
    const float* in  = (const float*)d_in[0];
    float*       out = (float*)d_out;
    dim3 grid(H / TRB, NIMG);       // (32, 48) = 1536 blocks
    MedianFilter_22737556865485_kernel<<<grid, BLOCK>>>(in, out);
}

// round 13
// speedup vs baseline: 1.3468x; 1.0597x over previous
#include <cuda_runtime.h>
#include <cstdint>

#define H 512
#define W 512
#define NIMG 48
#define TRB 16                  // output rows per block band
#define BLOCK 256
#define RD 8                    // smem ring depth (rows)

__device__ __forceinline__ float med3f(float a, float b, float c) {
    return fmaxf(fminf(a, b), fminf(fmaxf(a, b), c));
}

__device__ __forceinline__ void cp16(uint32_t daddr, const float* g) {
    asm volatile("cp.async.ca.shared.global [%0], [%1], 16;" :: "r"(daddr), "l"(g) : "memory");
}
__device__ __forceinline__ void cp_commit() {
    asm volatile("cp.async.commit_group;" ::: "memory");
}
template <int N> __device__ __forceinline__ void cp_wait() {
    asm volatile("cp.async.wait_group %0;" :: "n"(N) : "memory");
}

__global__ __launch_bounds__(BLOCK)
void MedianFilter_22737556865485_kernel(const float* __restrict__ in,
                                        float* __restrict__ out) {
    // 4-word guards front/back so the (SEL-discarded) edge LDS at word -1 / +512 stays in-bounds.
    __shared__ float smem[4 + RD * W + 4];
    float* const ring = smem + 4;

    const int t    = threadIdx.x;
    const int r0   = blockIdx.x * TRB;
    const int img  = blockIdx.y;
    const bool t0  = (t == 0), t255 = (t == BLOCK - 1);

    const float* base  = in  + (size_t)img * (H * W);
    float*       obase = out + (size_t)img * (H * W);

    const uint32_t sb = (uint32_t)__cvta_generic_to_shared(ring);
    const int rr = t >> 7;          // which of the 2 rows this thread fills
    const int k  = t & 127;         // 16B chunk within the row

    // gmem row pointer for ring index j (row r0-1+j), reflected at both image edges.
    auto gRow = [&](int j) -> const float* {
        int g = r0 - 1 + j;
        g = (g < 0) ? 1 : g;
        g = (g >= H) ? (2 * H - 2 - g) : g;
        return base + (size_t)g * W;
    };
    // Fill rows (j, j+1) as one commit group: 256 threads x 16B, fully coalesced.
    auto fill2 = [&](int j) {
        const int jj = j + rr;
        cp16(sb + (uint32_t)(((jj & (RD - 1)) * W + k * 4) * 4), gRow(jj) + k * 4);
        cp_commit();
    };

    // Prologue: 3 groups in flight — rows 0..5 (G0:{0,1} G1:{2,3} G2:{4,5}).
    fill2(0);
    fill2(2);
    fill2(4);

    // Row-triple history (per pixel column): lo/mi/hi over 3 horizontal neighbors.
    // mid computed on the FMA pipe: mid = (a+b+c) - min3 - max3.
    float loA[3], miA[3], hiA[3];   // px col 2t
    float loB[3], miB[3], hiB[3];   // px col 2t+1

    auto triple = [&](int j) {      // j, j%3 compile-time under full unroll
        const float* rowp = ring + (j & (RD - 1)) * W;
        const float2 m = *reinterpret_cast<const float2*>(rowp + 2 * t);
        const float a = t0   ? m.y : rowp[2 * t - 1];   // reflect col -1 -> 1
        const float d = t255 ? m.x : rowp[2 * t + 2];   // reflect col W -> W-2
        const int h = j % 3;
        const float sA = (a + m.x) + m.y;               // FMA pipe
        const float sB = (m.x + m.y) + d;               // FMA pipe
        loA[h] = fminf(fminf(a, m.x), m.y);             // ALU pipe
        hiA[h] = fmaxf(fmaxf(a, m.x), m.y);
        miA[h] = (sA - loA[h]) - hiA[h];                // FMA pipe
        loB[h] = fminf(fminf(m.x, m.y), d);
        hiB[h] = fmaxf(fmaxf(m.x, m.y), d);
        miB[h] = (sB - loB[h]) - hiB[h];                // FMA pipe
    };
    auto combine = [&](float2* po) {
        const float A0 = fmaxf(fmaxf(loA[0], loA[1]), loA[2]);  // max of mins
        const float C0 = fminf(fminf(hiA[0], hiA[1]), hiA[2]);  // min of maxes
        const float B0 = med3f(miA[0], miA[1], miA[2]);         // med of mids
        const float A1 = fmaxf(fmaxf(loB[0], loB[1]), loB[2]);
        const float C1 = fminf(fminf(hiB[0], hiB[1]), hiB[2]);
        const float B1 = med3f(miB[0], miB[1], miB[2]);
        *po = make_float2(med3f(A0, B0, C0), med3f(A1, B1, C1));
    };

    // Prime history with rows j=0,1 (G0 complete after wait<2>).
    cp_wait<2>();
    __syncthreads();
    triple(0);
    triple(1);

    float* po = obase + (size_t)r0 * W + 2 * t;

#pragma unroll
    for (int i = 0; i < TRB / 2; ++i) {
        // Steady state keeps 2 groups in flight: iter i fills rows {2i+6, 2i+7},
        // then waits for G_{i+1} (rows {2i+2, 2i+3}) — ~2 iterations of cover.
        if (i < TRB / 2 - 3) {
            fill2(2 * i + 6);
            cp_wait<2>();
        } else if (i == TRB / 2 - 3) {
            fill2(2 * i + 6);       // last fill: G8 = rows {16, 17}
            cp_wait<2>();
        } else if (i == TRB / 2 - 2) {
            cp_wait<1>();
        } else {
            cp_wait<0>();
        }
        __syncthreads();

        triple(2 * i + 2);          // row r0+2i+1
        combine(reinterpret_cast<float2*>(po));          // output row r0+2i
        triple(2 * i + 3);          // row r0+2i+2
        combine(reinterpret_cast<float2*>(po + W));      // output row r0+2i+1
        po += 2 * W;
    }
}

extern "C" void kernel_launch(void* const* d_in, const int* in_sizes, int n_in,
                              void* d_out, int out_size) {
    const float* in  = (const float*)d_in[0];
    float*       out = (float*)d_out;
    dim3 grid(H / TRB, NIMG);       // (32, 48) = 1536 blocks
    MedianFilter_22737556865485_kernel<<<grid, BLOCK>>>(in, out);
}